// round 1
// baseline (speedup 1.0000x reference)
#include <cuda_runtime.h>

#define SS 256
#define BATCH 2
#define HIDN 512
#define NHEAD 8
#define HDIM 64
#define NTOK 512
#define EPSF 1e-15f
#define CLIP1 0.9999999f
#define MAXNORM 0.996f

// ---------------- device scratch (no cudaMalloc allowed) ----------------
__device__ __align__(256) float g_mx[3 * NTOK * HIDN];          // 3 MB
__device__ __align__(256) float g_q[BATCH * NHEAD * SS * HDIM]; // 1 MB
__device__ __align__(256) float g_k[BATCH * NHEAD * SS * HDIM];
__device__ __align__(256) float g_gv[BATCH * NHEAD * SS * HDIM];
__device__ __align__(256) float g_x2[BATCH * NHEAD * SS];
__device__ __align__(256) float g_y2[BATCH * NHEAD * SS];
__device__ __align__(256) float g_gm1[BATCH * NHEAD * SS];
__device__ __align__(256) float g_probs[BATCH * NHEAD * SS * SS]; // 4 MB
__device__ __align__(256) float g_u[BATCH * SS * HIDN];

static __device__ __forceinline__ float frcp(float x) {
    float r; asm("rcp.approx.f32 %0, %1;" : "=f"(r) : "f"(x)); return r;
}
static __device__ __forceinline__ float frsq(float x) {
    float r; asm("rsqrt.approx.f32 %0, %1;" : "=f"(r) : "f"(x)); return r;
}

// block reduce for 512 threads (16 warps); sh must have >= 16 floats
static __device__ __forceinline__ float bred512(float v, float* sh) {
    int lane = threadIdx.x & 31, wid = threadIdx.x >> 5;
#pragma unroll
    for (int o = 16; o > 0; o >>= 1) v += __shfl_xor_sync(0xffffffffu, v, o);
    if (lane == 0) sh[wid] = v;
    __syncthreads();
    if (wid == 0) {
        float t = (lane < 16) ? sh[lane] : 0.f;
#pragma unroll
        for (int o = 8; o > 0; o >>= 1) t += __shfl_xor_sync(0xffffffffu, t, o);
        if (lane == 0) sh[0] = t;
    }
    __syncthreads();
    float r = sh[0];
    __syncthreads();
    return r;
}

// ---------------- kernel 1: mx = x @ W^T for 3 matrices ----------------
// grid (24, 8), block 256.  blockIdx.x: p = bx>>3, n-tile = bx&7. blockIdx.y: m-tile.
__global__ __launch_bounds__(256) void k_gemm(const float* __restrict__ X,
                                              const float* __restrict__ Wq,
                                              const float* __restrict__ Wk,
                                              const float* __restrict__ Wv) {
    __shared__ float As[16][64];
    __shared__ float Bs[16][64];
    int p = blockIdx.x >> 3;
    int n0 = (blockIdx.x & 7) * 64;
    int m0 = blockIdx.y * 64;
    const float* W = (p == 0) ? Wq : ((p == 1) ? Wk : Wv);
    int tid = threadIdx.x;
    int tx = tid & 15, ty = tid >> 4;
    int lr = tid >> 2, lc = (tid & 3) * 4;

    float acc[4][4];
#pragma unroll
    for (int i = 0; i < 4; i++)
#pragma unroll
        for (int j = 0; j < 4; j++) acc[i][j] = 0.f;

    for (int k0 = 0; k0 < 512; k0 += 16) {
        float4 av = *(const float4*)(X + (m0 + lr) * 512 + k0 + lc);
        float4 bv = *(const float4*)(W + (n0 + lr) * 512 + k0 + lc);
        As[lc + 0][lr] = av.x; As[lc + 1][lr] = av.y; As[lc + 2][lr] = av.z; As[lc + 3][lr] = av.w;
        Bs[lc + 0][lr] = bv.x; Bs[lc + 1][lr] = bv.y; Bs[lc + 2][lr] = bv.z; Bs[lc + 3][lr] = bv.w;
        __syncthreads();
#pragma unroll
        for (int kk = 0; kk < 16; kk++) {
            float4 a = *(const float4*)&As[kk][ty * 4];
            float4 b = *(const float4*)&Bs[kk][tx * 4];
            acc[0][0] = fmaf(a.x, b.x, acc[0][0]); acc[0][1] = fmaf(a.x, b.y, acc[0][1]);
            acc[0][2] = fmaf(a.x, b.z, acc[0][2]); acc[0][3] = fmaf(a.x, b.w, acc[0][3]);
            acc[1][0] = fmaf(a.y, b.x, acc[1][0]); acc[1][1] = fmaf(a.y, b.y, acc[1][1]);
            acc[1][2] = fmaf(a.y, b.z, acc[1][2]); acc[1][3] = fmaf(a.y, b.w, acc[1][3]);
            acc[2][0] = fmaf(a.z, b.x, acc[2][0]); acc[2][1] = fmaf(a.z, b.y, acc[2][1]);
            acc[2][2] = fmaf(a.z, b.z, acc[2][2]); acc[2][3] = fmaf(a.z, b.w, acc[2][3]);
            acc[3][0] = fmaf(a.w, b.x, acc[3][0]); acc[3][1] = fmaf(a.w, b.y, acc[3][1]);
            acc[3][2] = fmaf(a.w, b.z, acc[3][2]); acc[3][3] = fmaf(a.w, b.w, acc[3][3]);
        }
        __syncthreads();
    }
    float* out = g_mx + p * (NTOK * HIDN);
#pragma unroll
    for (int i = 0; i < 4; i++) {
        float4 v = make_float4(acc[i][0], acc[i][1], acc[i][2], acc[i][3]);
        *(float4*)(out + (m0 + ty * 4 + i) * 512 + n0 + tx * 4) = v;
    }
}

// ---------------- kernel 2: per-token manifold nonlinearity ----------------
// grid (512, 3), block 512.
__global__ __launch_bounds__(512) void k_token(const float* __restrict__ query,
                                               const float* __restrict__ bq,
                                               const float* __restrict__ bk,
                                               const float* __restrict__ bv) {
    __shared__ float sh[16];
    int tt = blockIdx.x, p = blockIdx.y, c = threadIdx.x;
    const float* bias = (p == 0) ? bq : ((p == 1) ? bk : bv);

    float x  = query[tt * 512 + c];
    float mx = g_mx[p * (NTOK * HIDN) + tt * 512 + c];
    float bb = bias[c];

    float sxx = bred512(x * x, sh);
    float smm = bred512(mx * mx, sh);
    float b2  = bred512(bb * bb, sh);

    float xn = fmaxf(sqrtf(sxx), EPSF);
    float mn = fmaxf(sqrtf(smm), EPSF);
    float sc = tanhf(mn / xn * atanhf(fminf(xn, CLIP1))) / mn;
    float res = sc * mx;

    float rb = bred512(res * bb, sh);
    float rr = bred512(res * res, sh);

    float A  = 1.f + 2.f * rb + b2;
    float Bc = 1.f - rr;
    float den = fmaxf(1.f + 2.f * rb + rr * b2, EPSF);
    float y = (A * res + Bc * bb) / den;

    float n2 = bred512(y * y, sh);
    float n = fmaxf(sqrtf(n2), EPSF);
    if (n > MAXNORM) { y *= MAXNORM / n; n = MAXNORM; }

    float lf = atanhf(fminf(n, CLIP1)) / n;
    float u = lf * y;

    // per-64 chunk expmap0
    float uu = u * u;
#pragma unroll
    for (int o = 16; o > 0; o >>= 1) uu += __shfl_xor_sync(0xffffffffu, uu, o);
    int lane = c & 31, wid = c >> 5;
    if (lane == 0) sh[wid] = uu;
    __syncthreads();
    int chunk = c >> 6;
    float cs = sh[chunk * 2] + sh[chunk * 2 + 1];
    float n64 = fmaxf(sqrtf(cs), EPSF);
    float t = tanhf(n64);
    float e = t / n64 * u;

    int s = tt >> 1, b = tt & 1;
    int h = s >> 5, s2 = ((s & 31) << 3) | chunk, d = c & 63;
    int hidx = (b * NHEAD + h) * SS + s2;
    int idx = hidx * 64 + d;
    if (p == 0) {
        g_q[idx] = e;
        if (d == 0) g_x2[hidx] = t * t;
    } else if (p == 1) {
        g_k[idx] = e;
        if (d == 0) g_y2[hidx] = t * t;
    } else {
        float gamma = 2.f / fmaxf(1.f - t * t, EPSF);
        g_gv[idx] = gamma * e;
        if (d == 0) g_gm1[hidx] = gamma - 1.f;
    }
}

// ---------------- kernel 3: pairwise scores -> probs ----------------
// grid (8 qtiles, 8 heads, 2 batch), block 256.  QT=32.
// smem: kl padded [256][68] + y2[256]  = 70656 B
__global__ __launch_bounds__(256) void k_scores(float* __restrict__ dout_probs, int wdo) {
    extern __shared__ float sm[];
    float* s_kl = sm;               // 256*68 floats
    float* s_y2 = sm + 256 * 68;    // 256 floats
    int b = blockIdx.z, h = blockIdx.y, qt = blockIdx.x;
    int bh = b * NHEAD + h;
    int tid = threadIdx.x;

    const float4* gk4 = (const float4*)(g_k) + bh * SS * 16;
    float4* skl4 = (float4*)s_kl;
    for (int i = tid; i < SS * 16; i += 256) {
        int n = i >> 4, d4 = i & 15;
        skl4[n * 17 + d4] = gk4[i];
    }
    for (int i = tid; i < SS; i += 256) s_y2[i] = g_y2[bh * SS + i];
    __syncthreads();

    int q = qt * 32 + (tid >> 3);
    int nset = tid & 7;

    float4 xq[16];
    const float4* gq4 = (const float4*)(g_q) + (bh * SS + q) * 16;
#pragma unroll
    for (int i = 0; i < 16; i++) xq[i] = gq4[i];
    float x2 = g_x2[bh * SS + q];
    float Bc = 1.f - x2;

    float* pg = g_probs + (bh * SS + q) * SS;
    float* pd = wdo ? (dout_probs + (bh * SS + q) * SS) : (float*)0;

#pragma unroll 1
    for (int j = 0; j < 32; j++) {
        int n = nset + (j << 3);
        const float4* kr = skl4 + n * 17;
        float4 kv[16];
#pragma unroll
        for (int i = 0; i < 16; i++) kv[i] = kr[i];

        float a0 = 0.f, a1 = 0.f, a2 = 0.f, a3 = 0.f;
#pragma unroll
        for (int i = 0; i < 16; i++) {
            a0 = fmaf(xq[i].x, kv[i].x, a0);
            a1 = fmaf(xq[i].y, kv[i].y, a1);
            a2 = fmaf(xq[i].z, kv[i].z, a2);
            a3 = fmaf(xq[i].w, kv[i].w, a3);
        }
        float xy = -((a0 + a1) + (a2 + a3));
        float y2 = s_y2[n];
        float base = fmaf(2.f, xy, 1.f);
        float A = base + y2;
        float den = fmaxf(fmaf(x2, y2, base), EPSF);
        float iv = frcp(den);
        float aa = -(A * iv);   // multiplies ql  (diff = aa*ql + bbs*kl)
        float bbs = Bc * iv;

        float s0 = 0.f, s1 = 0.f, s2 = 0.f, s3 = 0.f;
#pragma unroll
        for (int i = 0; i < 16; i++) {
            float d0 = fmaf(bbs, kv[i].x, aa * xq[i].x);
            float d1 = fmaf(bbs, kv[i].y, aa * xq[i].y);
            float d2 = fmaf(bbs, kv[i].z, aa * xq[i].z);
            float d3 = fmaf(bbs, kv[i].w, aa * xq[i].w);
            s0 += frcp(fmaxf(d0 * d0, 1e-30f));
            s1 += frcp(fmaxf(d1 * d1, 1e-30f));
            s2 += frcp(fmaxf(d2 * d2, 1e-30f));
            s3 += frcp(fmaxf(d3 * d3, 1e-30f));
        }
        float t1 = frsq((s0 + s1) + (s2 + s3));
        // sigmoid(-2*artanh(min(t1, 1-1e-7))) == (1 - min(t1, 1-1e-7)) / 2
        float prob = 0.5f * (1.f - fminf(t1, CLIP1));
        pg[n] = prob;
        if (pd) pd[n] = prob;
    }
}

// ---------------- kernel 4: gyro-midpoint + mobius_scalar_mul + logmap0 ----------------
// grid (16 qtiles, 8, 2), block 256.
// smem: gv padded [256][68] + gm1[256] + probs[16][256] = 87040 B
__global__ __launch_bounds__(256) void k_mid() {
    extern __shared__ float sm[];
    float* s_gv = sm;                 // 256*68
    float* s_g1 = sm + 256 * 68;      // 256
    float* s_p  = s_g1 + 256;         // 16*256
    int b = blockIdx.z, h = blockIdx.y, qt = blockIdx.x;
    int bh = b * NHEAD + h;
    int tid = threadIdx.x;
    int q0 = qt * 16;

    const float4* gg4 = (const float4*)(g_gv) + bh * SS * 16;
    float4* sg4 = (float4*)s_gv;
    for (int i = tid; i < SS * 16; i += 256) {
        int n = i >> 4, d4 = i & 15;
        sg4[n * 17 + d4] = gg4[i];
    }
    for (int i = tid; i < SS; i += 256) s_g1[i] = g_gm1[bh * SS + i];
    for (int i = tid; i < 16 * SS; i += 256) s_p[i] = g_probs[(bh * SS + q0) * SS + i];
    __syncthreads();

    int q = tid >> 4, d4 = tid & 15;
    const float* prow = s_p + q * SS;
    float ax = 0.f, ay = 0.f, az = 0.f, aw = 0.f, ad = 0.f;
#pragma unroll 4
    for (int n = 0; n < SS; n++) {
        float p = prow[n];
        float4 gv = sg4[n * 17 + d4];
        ax = fmaf(p, gv.x, ax);
        ay = fmaf(p, gv.y, ay);
        az = fmaf(p, gv.z, az);
        aw = fmaf(p, gv.w, aw);
        ad = fmaf(p, s_g1[n], ad);
    }
    float dn = fmaxf(fabsf(ad), 1e-10f);
    if (ad < 0.f) dn = -dn;
    float idn = 1.f / dn;
    float m0 = ax * idn, m1 = ay * idn, m2 = az * idn, m3 = aw * idn;
    float nn = m0 * m0 + m1 * m1 + m2 * m2 + m3 * m3;
#pragma unroll
    for (int o = 1; o < 16; o <<= 1) nn += __shfl_xor_sync(0xffffffffu, nn, o);
    float nm = fmaxf(sqrtf(nn), EPSF);
    // logmap0(mobius_scalar_mul(0.5, m)) == 0.5*artanh(min(nm,1-1e-7)) * m / nm
    float f = 0.5f * atanhf(fminf(nm, CLIP1)) / nm;
    float4 u = make_float4(f * m0, f * m1, f * m2, f * m3);
    *(float4*)(g_u + (b * SS + q0 + q) * HIDN + h * 64 + d4 * 4) = u;
}

// ---------------- kernel 5: final expmap0 over 512 + output transpose ----------------
// grid 512 (token = b*256+q), block 512.
__global__ __launch_bounds__(512) void k_final(float* __restrict__ out) {
    __shared__ float sh[16];
    int t = blockIdx.x;
    int b = t >> 8, q = t & 255;
    int c = threadIdx.x;
    float u = g_u[t * HIDN + c];
    float n2 = bred512(u * u, sh);
    float n = fmaxf(sqrtf(n2), EPSF);
    float f = tanhf(n) / n;
    out[(q * BATCH + b) * HIDN + c] = f * u;
}

// ---------------- launch ----------------
extern "C" void kernel_launch(void* const* d_in, const int* in_sizes, int n_in,
                              void* d_out, int out_size) {
    const float* query = (const float*)d_in[0];
    const float* Wq = (const float*)d_in[1];
    const float* bq = (const float*)d_in[2];
    const float* Wk = (const float*)d_in[3];
    const float* bk = (const float*)d_in[4];
    const float* Wv = (const float*)d_in[5];
    const float* bv = (const float*)d_in[6];
    float* out = (float*)d_out;

    const int CTXN = SS * BATCH * HIDN;              // 262144
    const int PRN = BATCH * NHEAD * SS * SS;         // 1048576
    float* dctx = 0;
    float* dpro = 0;
    if (out_size >= CTXN + PRN) { dctx = out; dpro = out + CTXN; }
    else if (out_size == PRN)   { dpro = out; }
    else                        { dctx = out; }

    const int SMEM_SCORES = (256 * 68 + 256) * 4;              // 70656
    const int SMEM_MID    = (256 * 68 + 256 + 16 * 256) * 4;   // 87040
    cudaFuncSetAttribute(k_scores, cudaFuncAttributeMaxDynamicSharedMemorySize, SMEM_SCORES);
    cudaFuncSetAttribute(k_mid,    cudaFuncAttributeMaxDynamicSharedMemorySize, SMEM_MID);

    k_gemm<<<dim3(24, 8), 256>>>(query, Wq, Wk, Wv);
    k_token<<<dim3(512, 3), 512>>>(query, bq, bk, bv);
    k_scores<<<dim3(8, 8, 2), 256, SMEM_SCORES>>>(dpro, dpro ? 1 : 0);
    k_mid<<<dim3(16, 8, 2), 256, SMEM_MID>>>();
    if (dctx) k_final<<<512, 512>>>(dctx);
}

// round 2
// speedup vs baseline: 1.1343x; 1.1343x over previous
#include <cuda_runtime.h>

#define SS 256
#define BATCH 2
#define HIDN 512
#define NHEAD 8
#define HDIM 64
#define NTOK 512
#define EPSF 1e-15f
#define CLIP1 0.9999999f
#define MAXNORM 0.996f
#define KSPLIT 4
#define NSPLIT 2

// ---------------- device scratch (no cudaMalloc allowed) ----------------
__device__ __align__(256) float g_mxp[KSPLIT * 3 * NTOK * HIDN];   // 12.6 MB partials
__device__ __align__(256) float g_q[BATCH * NHEAD * SS * HDIM];
__device__ __align__(256) float g_k[BATCH * NHEAD * SS * HDIM];
__device__ __align__(256) float g_gv[BATCH * NHEAD * SS * HDIM];
__device__ __align__(256) float g_x2[BATCH * NHEAD * SS];
__device__ __align__(256) float g_y2[BATCH * NHEAD * SS];
__device__ __align__(256) float g_gm1[BATCH * NHEAD * SS];
__device__ __align__(256) float g_probs[BATCH * NHEAD * SS * SS];  // fallback probs
__device__ __align__(256) float g_nomp[NSPLIT][BATCH * NHEAD * SS * HDIM];
__device__ __align__(256) float g_denp[NSPLIT][BATCH * NHEAD * SS];

static __device__ __forceinline__ float frcp(float x) {
    float r; asm("rcp.approx.f32 %0, %1;" : "=f"(r) : "f"(x)); return r;
}
static __device__ __forceinline__ float frsq(float x) {
    float r; asm("rsqrt.approx.f32 %0, %1;" : "=f"(r) : "f"(x)); return r;
}

// multi-value block reduction for 512 threads: reduces k values at once.
// sh must hold k*16 floats. After call, result j = sum over block of vals[j].
// One sync inside; caller must sync before reusing sh.
template <int K>
static __device__ __forceinline__ void bredK(float* vals, float* sh) {
    int lane = threadIdx.x & 31, wid = threadIdx.x >> 5;
#pragma unroll
    for (int j = 0; j < K; j++) {
        float v = vals[j];
#pragma unroll
        for (int o = 16; o > 0; o >>= 1) v += __shfl_xor_sync(0xffffffffu, v, o);
        if (lane == 0) sh[j * 16 + wid] = v;
    }
    __syncthreads();
#pragma unroll
    for (int j = 0; j < K; j++) {
        float t = 0.f;
#pragma unroll
        for (int i = 0; i < 16; i++) t += sh[j * 16 + i];
        vals[j] = t;
    }
}

// ---------------- kernel 1: mx = x @ W^T, K-split partials ----------------
// grid (24, 8, KSPLIT), block 256. bx: p = bx>>3, n-tile = bx&7; by: m-tile; bz: k-chunk.
__global__ __launch_bounds__(256) void k_gemm(const float* __restrict__ X,
                                              const float* __restrict__ Wq,
                                              const float* __restrict__ Wk,
                                              const float* __restrict__ Wv) {
    __shared__ float As[16][64];
    __shared__ float Bs[16][64];
    int p = blockIdx.x >> 3;
    int n0 = (blockIdx.x & 7) * 64;
    int m0 = blockIdx.y * 64;
    int kbase = blockIdx.z * (512 / KSPLIT);
    const float* W = (p == 0) ? Wq : ((p == 1) ? Wk : Wv);
    int tid = threadIdx.x;
    int tx = tid & 15, ty = tid >> 4;
    int lr = tid >> 2, lc = (tid & 3) * 4;

    float acc[4][4];
#pragma unroll
    for (int i = 0; i < 4; i++)
#pragma unroll
        for (int j = 0; j < 4; j++) acc[i][j] = 0.f;

    float4 av = *(const float4*)(X + (m0 + lr) * 512 + kbase + lc);
    float4 bv = *(const float4*)(W + (n0 + lr) * 512 + kbase + lc);

    const int NCH = (512 / KSPLIT) / 16;
#pragma unroll 1
    for (int ch = 0; ch < NCH; ch++) {
        As[lc + 0][lr] = av.x; As[lc + 1][lr] = av.y; As[lc + 2][lr] = av.z; As[lc + 3][lr] = av.w;
        Bs[lc + 0][lr] = bv.x; Bs[lc + 1][lr] = bv.y; Bs[lc + 2][lr] = bv.z; Bs[lc + 3][lr] = bv.w;
        __syncthreads();
        if (ch + 1 < NCH) {
            int k0 = kbase + (ch + 1) * 16;
            av = *(const float4*)(X + (m0 + lr) * 512 + k0 + lc);
            bv = *(const float4*)(W + (n0 + lr) * 512 + k0 + lc);
        }
#pragma unroll
        for (int kk = 0; kk < 16; kk++) {
            float4 a = *(const float4*)&As[kk][ty * 4];
            float4 b = *(const float4*)&Bs[kk][tx * 4];
            acc[0][0] = fmaf(a.x, b.x, acc[0][0]); acc[0][1] = fmaf(a.x, b.y, acc[0][1]);
            acc[0][2] = fmaf(a.x, b.z, acc[0][2]); acc[0][3] = fmaf(a.x, b.w, acc[0][3]);
            acc[1][0] = fmaf(a.y, b.x, acc[1][0]); acc[1][1] = fmaf(a.y, b.y, acc[1][1]);
            acc[1][2] = fmaf(a.y, b.z, acc[1][2]); acc[1][3] = fmaf(a.y, b.w, acc[1][3]);
            acc[2][0] = fmaf(a.z, b.x, acc[2][0]); acc[2][1] = fmaf(a.z, b.y, acc[2][1]);
            acc[2][2] = fmaf(a.z, b.z, acc[2][2]); acc[2][3] = fmaf(a.z, b.w, acc[2][3]);
            acc[3][0] = fmaf(a.w, b.x, acc[3][0]); acc[3][1] = fmaf(a.w, b.y, acc[3][1]);
            acc[3][2] = fmaf(a.w, b.z, acc[3][2]); acc[3][3] = fmaf(a.w, b.w, acc[3][3]);
        }
        __syncthreads();
    }
    float* out = g_mxp + blockIdx.z * (3 * NTOK * HIDN) + p * (NTOK * HIDN);
#pragma unroll
    for (int i = 0; i < 4; i++) {
        float4 v = make_float4(acc[i][0], acc[i][1], acc[i][2], acc[i][3]);
        *(float4*)(out + (m0 + ty * 4 + i) * 512 + n0 + tx * 4) = v;
    }
}

// ---------------- kernel 2: per-token manifold nonlinearity ----------------
// grid (512, 3), block 512.
__global__ __launch_bounds__(512) void k_token(const float* __restrict__ query,
                                               const float* __restrict__ bq,
                                               const float* __restrict__ bk,
                                               const float* __restrict__ bv) {
    __shared__ float sh[48];
    int tt = blockIdx.x, p = blockIdx.y, c = threadIdx.x;
    const float* bias = (p == 0) ? bq : ((p == 1) ? bk : bv);

    float x  = query[tt * 512 + c];
    int moff = p * (NTOK * HIDN) + tt * 512 + c;
    float mx = g_mxp[moff] + g_mxp[moff + 3 * NTOK * HIDN]
             + g_mxp[moff + 2 * 3 * NTOK * HIDN] + g_mxp[moff + 3 * 3 * NTOK * HIDN];
    float bb = bias[c];

    float r3[3] = {x * x, mx * mx, bb * bb};
    bredK<3>(r3, sh);
    __syncthreads();

    float xn = fmaxf(sqrtf(r3[0]), EPSF);
    float mn = fmaxf(sqrtf(r3[1]), EPSF);
    float b2 = r3[2];
    float sc = tanhf(mn / xn * atanhf(fminf(xn, CLIP1))) / mn;
    float res = sc * mx;

    float r2[2] = {res * bb, res * res};
    bredK<2>(r2, sh);
    __syncthreads();
    float rb = r2[0], rr = r2[1];

    float A  = 1.f + 2.f * rb + b2;
    float Bc = 1.f - rr;
    float den = fmaxf(1.f + 2.f * rb + rr * b2, EPSF);
    float y = (A * res + Bc * bb) / den;

    float r1[1] = {y * y};
    bredK<1>(r1, sh);
    __syncthreads();
    float n = fmaxf(sqrtf(r1[0]), EPSF);
    if (n > MAXNORM) { y *= MAXNORM / n; n = MAXNORM; }

    float lf = atanhf(fminf(n, CLIP1)) / n;
    float u = lf * y;

    // per-64 chunk expmap0
    float uu = u * u;
#pragma unroll
    for (int o = 16; o > 0; o >>= 1) uu += __shfl_xor_sync(0xffffffffu, uu, o);
    int lane = c & 31, wid = c >> 5;
    if (lane == 0) sh[wid] = uu;
    __syncthreads();
    int chunk = c >> 6;
    float cs = sh[chunk * 2] + sh[chunk * 2 + 1];
    float n64 = fmaxf(sqrtf(cs), EPSF);
    float t = tanhf(n64);
    float e = t / n64 * u;

    int s = tt >> 1, b = tt & 1;
    int h = s >> 5, s2 = ((s & 31) << 3) | chunk, d = c & 63;
    int hidx = (b * NHEAD + h) * SS + s2;
    int idx = hidx * 64 + d;
    if (p == 0) {
        g_q[idx] = e;
        if (d == 0) g_x2[hidx] = t * t;
    } else if (p == 1) {
        g_k[idx] = e;
        if (d == 0) g_y2[hidx] = t * t;
    } else {
        float gamma = 2.f / fmaxf(1.f - t * t, EPSF);
        g_gv[idx] = gamma * e;
        if (d == 0) g_gm1[hidx] = gamma - 1.f;
    }
}

// ---------------- kernel 3: pairwise scores -> probs ----------------
// grid (8 qtiles, 8 heads, 2 batch), block 256.  QT=32.
__global__ __launch_bounds__(256) void k_scores(float* __restrict__ probs) {
    extern __shared__ float sm[];
    float* s_kl = sm;               // 256*68 floats
    float* s_y2 = sm + 256 * 68;    // 256 floats
    int b = blockIdx.z, h = blockIdx.y, qt = blockIdx.x;
    int bh = b * NHEAD + h;
    int tid = threadIdx.x;

    const float4* gk4 = (const float4*)(g_k) + bh * SS * 16;
    float4* skl4 = (float4*)s_kl;
    for (int i = tid; i < SS * 16; i += 256) {
        int n = i >> 4, d4 = i & 15;
        skl4[n * 17 + d4] = gk4[i];
    }
    for (int i = tid; i < SS; i += 256) s_y2[i] = g_y2[bh * SS + i];
    __syncthreads();

    int q = qt * 32 + (tid >> 3);
    int nset = tid & 7;

    float4 xq[16];
    const float4* gq4 = (const float4*)(g_q) + (bh * SS + q) * 16;
#pragma unroll
    for (int i = 0; i < 16; i++) xq[i] = gq4[i];
    float x2 = g_x2[bh * SS + q];
    float Bc = 1.f - x2;

    float* pg = probs + (bh * SS + q) * SS;

#pragma unroll 1
    for (int j = 0; j < 32; j++) {
        int n = nset + (j << 3);
        const float4* kr = skl4 + n * 17;
        float4 kv[16];
#pragma unroll
        for (int i = 0; i < 16; i++) kv[i] = kr[i];

        float a0 = 0.f, a1 = 0.f, a2 = 0.f, a3 = 0.f;
#pragma unroll
        for (int i = 0; i < 16; i++) {
            a0 = fmaf(xq[i].x, kv[i].x, a0);
            a1 = fmaf(xq[i].y, kv[i].y, a1);
            a2 = fmaf(xq[i].z, kv[i].z, a2);
            a3 = fmaf(xq[i].w, kv[i].w, a3);
        }
        float xy = -((a0 + a1) + (a2 + a3));
        float y2 = s_y2[n];
        float base = fmaf(2.f, xy, 1.f);
        float A = base + y2;
        float den = fmaxf(fmaf(x2, y2, base), EPSF);
        float iv = frcp(den);
        float aa = -(A * iv);
        float bbs = Bc * iv;

        float s0 = 0.f, s1 = 0.f, s2 = 0.f, s3 = 0.f;
#pragma unroll
        for (int i = 0; i < 16; i++) {
            float d0 = fmaf(bbs, kv[i].x, aa * xq[i].x);
            float d1 = fmaf(bbs, kv[i].y, aa * xq[i].y);
            float d2 = fmaf(bbs, kv[i].z, aa * xq[i].z);
            float d3 = fmaf(bbs, kv[i].w, aa * xq[i].w);
            s0 += frcp(fmaxf(d0 * d0, 1e-30f));
            s1 += frcp(fmaxf(d1 * d1, 1e-30f));
            s2 += frcp(fmaxf(d2 * d2, 1e-30f));
            s3 += frcp(fmaxf(d3 * d3, 1e-30f));
        }
        float t1 = frsq((s0 + s1) + (s2 + s3));
        // sigmoid(-2*artanh(min(t1, 1-1e-7))) == (1 - min(t1, 1-1e-7)) / 2
        pg[n] = 0.5f * (1.f - fminf(t1, CLIP1));
    }
}

// ---------------- kernel 4: n-split gyro-midpoint partial sums ----------------
// grid (16 qtiles, 16 bh, NSPLIT), block 256 = (q 0..15) x (d4 0..15).
// smem 43.5 KB static -> 5 CTAs/SM.
__global__ __launch_bounds__(256) void k_mid(const float* __restrict__ probs) {
    __shared__ float s_gv[128 * 17 * 4];   // 128 n x 16 float4, pad 17
    __shared__ float s_p[16 * 128];        // 16 q  x 128 n
    __shared__ float s_g1[128];
    int qt = blockIdx.x, bh = blockIdx.y, ns = blockIdx.z;
    int tid = threadIdx.x;
    int q0 = qt * 16, n0 = ns * 128;

    const float4* gg4 = (const float4*)(g_gv) + bh * SS * 16;
    float4* sg4 = (float4*)s_gv;
#pragma unroll
    for (int it = 0; it < 8; it++) {
        int i = tid + it * 256;
        int n = i >> 4, d4 = i & 15;
        sg4[n * 17 + d4] = gg4[(n0 + n) * 16 + d4];
    }
    const float4* gp4 = (const float4*)(probs);
    float4* sp4 = (float4*)s_p;
#pragma unroll
    for (int it = 0; it < 2; it++) {
        int i = tid + it * 256;             // i in [0,512)
        int q = i >> 5, j = i & 31;
        sp4[q * 32 + j] = gp4[(bh * SS + q0 + q) * 64 + (n0 >> 2) + j];
    }
    for (int i = tid; i < 128; i += 256) s_g1[i] = g_gm1[bh * SS + n0 + i];
    __syncthreads();

    int q = tid >> 4, d4 = tid & 15;
    const float* prow = s_p + q * 128;
    float ax = 0.f, ay = 0.f, az = 0.f, aw = 0.f, ad = 0.f;
#pragma unroll 4
    for (int n = 0; n < 128; n++) {
        float p = prow[n];
        float4 gv = sg4[n * 17 + d4];
        ax = fmaf(p, gv.x, ax);
        ay = fmaf(p, gv.y, ay);
        az = fmaf(p, gv.z, az);
        aw = fmaf(p, gv.w, aw);
        ad = fmaf(p, s_g1[n], ad);
    }
    int row = bh * SS + q0 + q;
    *(float4*)(&g_nomp[ns][row * 64 + d4 * 4]) = make_float4(ax, ay, az, aw);
    if (d4 == 0) g_denp[ns][row] = ad;
}

// ---------------- kernel 5: midpoint epilogue + expmap0 + transpose ----------------
// grid 512 (t = b*256+q), block 512.
__global__ __launch_bounds__(512) void k_final(float* __restrict__ out) {
    __shared__ float sh[16];
    int t = blockIdx.x;
    int b = t >> 8, q = t & 255;
    int c = threadIdx.x;
    int h = c >> 6, d = c & 63;
    int row = ((b * NHEAD + h) << 8) + q;

    float m = g_nomp[0][row * 64 + d] + g_nomp[1][row * 64 + d];
    float dn0 = g_denp[0][row] + g_denp[1][row];
    float dn = fmaxf(fabsf(dn0), 1e-10f);
    if (dn0 < 0.f) dn = -dn;
    m = m / dn;

    // per-64 chunk: mobius_scalar_mul(0.5) + logmap0 => 0.5*artanh(min(nm,clip))*m/nm
    float nn = m * m;
#pragma unroll
    for (int o = 16; o > 0; o >>= 1) nn += __shfl_xor_sync(0xffffffffu, nn, o);
    int lane = c & 31, wid = c >> 5;
    if (lane == 0) sh[wid] = nn;
    __syncthreads();
    float nm2 = sh[h * 2] + sh[h * 2 + 1];
    float nm = fmaxf(sqrtf(nm2), EPSF);
    float f = 0.5f * atanhf(fminf(nm, CLIP1)) / nm;
    float u = f * m;
    __syncthreads();

    // full-512 expmap0
    float uu = u * u;
#pragma unroll
    for (int o = 16; o > 0; o >>= 1) uu += __shfl_xor_sync(0xffffffffu, uu, o);
    if (lane == 0) sh[wid] = uu;
    __syncthreads();
    float tot = 0.f;
#pragma unroll
    for (int i = 0; i < 16; i++) tot += sh[i];
    float n = fmaxf(sqrtf(tot), EPSF);
    float f2 = tanhf(n) / n;
    out[(q * BATCH + b) * HIDN + c] = f2 * u;
}

// ---------------- launch ----------------
extern "C" void kernel_launch(void* const* d_in, const int* in_sizes, int n_in,
                              void* d_out, int out_size) {
    const float* query = (const float*)d_in[0];
    const float* Wq = (const float*)d_in[1];
    const float* bq = (const float*)d_in[2];
    const float* Wk = (const float*)d_in[3];
    const float* bk = (const float*)d_in[4];
    const float* Wv = (const float*)d_in[5];
    const float* bv = (const float*)d_in[6];
    float* out = (float*)d_out;

    const int CTXN = SS * BATCH * HIDN;              // 262144
    const int PRN = BATCH * NHEAD * SS * SS;         // 1048576
    float* dctx = 0;
    float* dpro = 0;
    if (out_size >= CTXN + PRN) { dctx = out; dpro = out + CTXN; }
    else if (out_size == PRN)   { dpro = out; }
    else                        { dctx = out; }

    float* probs_ptr = dpro ? dpro : (float*)0;

    const int SMEM_SCORES = (256 * 68 + 256) * 4;    // 70656
    cudaFuncSetAttribute(k_scores, cudaFuncAttributeMaxDynamicSharedMemorySize, SMEM_SCORES);

    k_gemm<<<dim3(24, 8, KSPLIT), 256>>>(query, Wq, Wk, Wv);
    k_token<<<dim3(512, 3), 512>>>(query, bq, bk, bv);
    if (probs_ptr) {
        k_scores<<<dim3(8, 8, 2), 256, SMEM_SCORES>>>(probs_ptr);
        if (dctx) {
            k_mid<<<dim3(16, 16, NSPLIT), 256>>>(probs_ptr);
            k_final<<<512, 512>>>(dctx);
        }
    } else {
        float* gp;
        cudaGetSymbolAddress((void**)&gp, g_probs);
        k_scores<<<dim3(8, 8, 2), 256, SMEM_SCORES>>>(gp);
        k_mid<<<dim3(16, 16, NSPLIT), 256>>>(gp);
        k_final<<<512, 512>>>(dctx);
    }
}

// round 3
// speedup vs baseline: 1.2545x; 1.1060x over previous
#include <cuda_runtime.h>

#define SS 256
#define BATCH 2
#define HIDN 512
#define NHEAD 8
#define HDIM 64
#define NTOK 512
#define EPSF 1e-15f
#define CLIP1 0.9999999f
#define MAXNORM 0.996f
#define KSPLIT 4
#define NSPLIT 4

// ---------------- device scratch ----------------
__device__ __align__(256) float g_mxp[KSPLIT * 3 * NTOK * HIDN];
__device__ __align__(256) float g_q[BATCH * NHEAD * SS * HDIM];
__device__ __align__(256) float g_k[BATCH * NHEAD * SS * HDIM];
__device__ __align__(256) float g_gv[BATCH * NHEAD * SS * HDIM];
__device__ __align__(256) float g_x2[BATCH * NHEAD * SS];
__device__ __align__(256) float g_y2[BATCH * NHEAD * SS];
__device__ __align__(256) float g_gm1[BATCH * NHEAD * SS];
__device__ __align__(256) float g_probs[BATCH * NHEAD * SS * SS];  // fallback
__device__ __align__(256) float g_nomp[NSPLIT][BATCH * NHEAD * SS * HDIM];

static __device__ __forceinline__ float frcp(float x) {
    float r; asm("rcp.approx.f32 %0, %1;" : "=f"(r) : "f"(x)); return r;
}
static __device__ __forceinline__ float frsq(float x) {
    float r; asm("rsqrt.approx.f32 %0, %1;" : "=f"(r) : "f"(x)); return r;
}

template <int K>
static __device__ __forceinline__ void bredK(float* vals, float* sh) {
    int lane = threadIdx.x & 31, wid = threadIdx.x >> 5;
#pragma unroll
    for (int j = 0; j < K; j++) {
        float v = vals[j];
#pragma unroll
        for (int o = 16; o > 0; o >>= 1) v += __shfl_xor_sync(0xffffffffu, v, o);
        if (lane == 0) sh[j * 16 + wid] = v;
    }
    __syncthreads();
#pragma unroll
    for (int j = 0; j < K; j++) {
        float t = 0.f;
#pragma unroll
        for (int i = 0; i < 16; i++) t += sh[j * 16 + i];
        vals[j] = t;
    }
}

// ---------------- kernel 1: mx = x @ W^T, K-split partials ----------------
__global__ __launch_bounds__(256) void k_gemm(const float* __restrict__ X,
                                              const float* __restrict__ Wq,
                                              const float* __restrict__ Wk,
                                              const float* __restrict__ Wv) {
    __shared__ float As[16][64];
    __shared__ float Bs[16][64];
    int p = blockIdx.x >> 3;
    int n0 = (blockIdx.x & 7) * 64;
    int m0 = blockIdx.y * 64;
    int kbase = blockIdx.z * (512 / KSPLIT);
    const float* W = (p == 0) ? Wq : ((p == 1) ? Wk : Wv);
    int tid = threadIdx.x;
    int tx = tid & 15, ty = tid >> 4;
    int lr = tid >> 2, lc = (tid & 3) * 4;

    float acc[4][4];
#pragma unroll
    for (int i = 0; i < 4; i++)
#pragma unroll
        for (int j = 0; j < 4; j++) acc[i][j] = 0.f;

    float4 av = *(const float4*)(X + (m0 + lr) * 512 + kbase + lc);
    float4 bv = *(const float4*)(W + (n0 + lr) * 512 + kbase + lc);

    const int NCH = (512 / KSPLIT) / 16;
#pragma unroll 1
    for (int ch = 0; ch < NCH; ch++) {
        As[lc + 0][lr] = av.x; As[lc + 1][lr] = av.y; As[lc + 2][lr] = av.z; As[lc + 3][lr] = av.w;
        Bs[lc + 0][lr] = bv.x; Bs[lc + 1][lr] = bv.y; Bs[lc + 2][lr] = bv.z; Bs[lc + 3][lr] = bv.w;
        __syncthreads();
        if (ch + 1 < NCH) {
            int k0 = kbase + (ch + 1) * 16;
            av = *(const float4*)(X + (m0 + lr) * 512 + k0 + lc);
            bv = *(const float4*)(W + (n0 + lr) * 512 + k0 + lc);
        }
#pragma unroll
        for (int kk = 0; kk < 16; kk++) {
            float4 a = *(const float4*)&As[kk][ty * 4];
            float4 b = *(const float4*)&Bs[kk][tx * 4];
            acc[0][0] = fmaf(a.x, b.x, acc[0][0]); acc[0][1] = fmaf(a.x, b.y, acc[0][1]);
            acc[0][2] = fmaf(a.x, b.z, acc[0][2]); acc[0][3] = fmaf(a.x, b.w, acc[0][3]);
            acc[1][0] = fmaf(a.y, b.x, acc[1][0]); acc[1][1] = fmaf(a.y, b.y, acc[1][1]);
            acc[1][2] = fmaf(a.y, b.z, acc[1][2]); acc[1][3] = fmaf(a.y, b.w, acc[1][3]);
            acc[2][0] = fmaf(a.z, b.x, acc[2][0]); acc[2][1] = fmaf(a.z, b.y, acc[2][1]);
            acc[2][2] = fmaf(a.z, b.z, acc[2][2]); acc[2][3] = fmaf(a.z, b.w, acc[2][3]);
            acc[3][0] = fmaf(a.w, b.x, acc[3][0]); acc[3][1] = fmaf(a.w, b.y, acc[3][1]);
            acc[3][2] = fmaf(a.w, b.z, acc[3][2]); acc[3][3] = fmaf(a.w, b.w, acc[3][3]);
        }
        __syncthreads();
    }
    float* out = g_mxp + blockIdx.z * (3 * NTOK * HIDN) + p * (NTOK * HIDN);
#pragma unroll
    for (int i = 0; i < 4; i++) {
        float4 v = make_float4(acc[i][0], acc[i][1], acc[i][2], acc[i][3]);
        *(float4*)(out + (m0 + ty * 4 + i) * 512 + n0 + tx * 4) = v;
    }
}

// ---------------- kernel 2: per-token manifold nonlinearity ----------------
__global__ __launch_bounds__(512) void k_token(const float* __restrict__ query,
                                               const float* __restrict__ bq,
                                               const float* __restrict__ bk,
                                               const float* __restrict__ bv) {
    __shared__ float sh[48];
    int tt = blockIdx.x, p = blockIdx.y, c = threadIdx.x;
    const float* bias = (p == 0) ? bq : ((p == 1) ? bk : bv);

    float x  = query[tt * 512 + c];
    int moff = p * (NTOK * HIDN) + tt * 512 + c;
    float mx = g_mxp[moff] + g_mxp[moff + 3 * NTOK * HIDN]
             + g_mxp[moff + 2 * 3 * NTOK * HIDN] + g_mxp[moff + 3 * 3 * NTOK * HIDN];
    float bb = bias[c];

    float r3[3] = {x * x, mx * mx, bb * bb};
    bredK<3>(r3, sh);
    __syncthreads();

    float xn = fmaxf(sqrtf(r3[0]), EPSF);
    float mn = fmaxf(sqrtf(r3[1]), EPSF);
    float b2 = r3[2];
    float sc = tanhf(mn / xn * atanhf(fminf(xn, CLIP1))) / mn;
    float res = sc * mx;

    float r2[2] = {res * bb, res * res};
    bredK<2>(r2, sh);
    __syncthreads();
    float rb = r2[0], rr = r2[1];

    float A  = 1.f + 2.f * rb + b2;
    float Bc = 1.f - rr;
    float den = fmaxf(1.f + 2.f * rb + rr * b2, EPSF);
    float y = (A * res + Bc * bb) / den;

    float r1[1] = {y * y};
    bredK<1>(r1, sh);
    __syncthreads();
    float n = fmaxf(sqrtf(r1[0]), EPSF);
    if (n > MAXNORM) { y *= MAXNORM / n; n = MAXNORM; }

    float lf = atanhf(fminf(n, CLIP1)) / n;
    float u = lf * y;

    float uu = u * u;
#pragma unroll
    for (int o = 16; o > 0; o >>= 1) uu += __shfl_xor_sync(0xffffffffu, uu, o);
    int lane = c & 31, wid = c >> 5;
    if (lane == 0) sh[wid] = uu;
    __syncthreads();
    int chunk = c >> 6;
    float cs = sh[chunk * 2] + sh[chunk * 2 + 1];
    float n64 = fmaxf(sqrtf(cs), EPSF);
    float t = tanhf(n64);
    float e = t / n64 * u;

    int s = tt >> 1, b = tt & 1;
    int h = s >> 5, s2 = ((s & 31) << 3) | chunk, d = c & 63;
    int hidx = (b * NHEAD + h) * SS + s2;
    int idx = hidx * 64 + d;
    if (p == 0) {
        g_q[idx] = e;
        if (d == 0) g_x2[hidx] = t * t;
    } else if (p == 1) {
        g_k[idx] = e;
        if (d == 0) g_y2[hidx] = t * t;
    } else {
        float gamma = 2.f / fmaxf(1.f - t * t, EPSF);
        g_gv[idx] = gamma * e;
        if (d == 0) g_gm1[hidx] = gamma - 1.f;
    }
}

// ---------------- kernel 3: pairwise scores -> probs (factored form) ----------------
// grid (8 qtiles, 8 heads, 2 batch), block 256.
__global__ __launch_bounds__(256) void k_scores(float* __restrict__ probs) {
    extern __shared__ float sm[];
    float* s_kl = sm;               // 256*68
    float* s_y2 = sm + 256 * 68;    // 256
    int b = blockIdx.z, h = blockIdx.y, qt = blockIdx.x;
    int bh = b * NHEAD + h;
    int tid = threadIdx.x;

    const float4* gk4 = (const float4*)(g_k) + bh * SS * 16;
    float4* skl4 = (float4*)s_kl;
    for (int i = tid; i < SS * 16; i += 256) {
        int n = i >> 4, d4 = i & 15;
        skl4[n * 17 + d4] = gk4[i];
    }
    for (int i = tid; i < SS; i += 256) s_y2[i] = g_y2[bh * SS + i];
    __syncthreads();

    int q = qt * 32 + (tid >> 3);
    int nset = tid & 7;

    float4 xq[16];
    const float4* gq4 = (const float4*)(g_q) + (bh * SS + q) * 16;
#pragma unroll
    for (int i = 0; i < 16; i++) xq[i] = gq4[i];
    float x2 = g_x2[bh * SS + q];
    float Bc = 1.f - x2;

    float* pg = probs + (bh * SS + q) * SS;

#pragma unroll 1
    for (int j = 0; j < 32; j++) {
        int n = nset + (j << 3);
        const float4* kr = skl4 + n * 17;

        // pass 1: dot(xq, kl)
        float a0 = 0.f, a1 = 0.f, a2 = 0.f, a3 = 0.f;
#pragma unroll
        for (int i = 0; i < 16; i++) {
            float4 kv = kr[i];
            a0 = fmaf(xq[i].x, kv.x, a0);
            a1 = fmaf(xq[i].y, kv.y, a1);
            a2 = fmaf(xq[i].z, kv.z, a2);
            a3 = fmaf(xq[i].w, kv.w, a3);
        }
        float xy = -((a0 + a1) + (a2 + a3));
        float y2 = s_y2[n];
        float base = fmaf(2.f, xy, 1.f);
        float A = base + y2;                       // > 0 (norms << 1)
        float den = fmaxf(fmaf(x2, y2, base), EPSF);
        float Aiv = A * frcp(den);                 // = |aa|
        float r = -Bc * frcp(A);                   // bbs/aa

        // pass 2: sum of reciprocals of e^2, e = xq + r*kl  (d = aa*e)
        float s0 = 0.f, s1 = 0.f, s2 = 0.f, s3 = 0.f;
#pragma unroll
        for (int i = 0; i < 16; i++) {
            float4 kv = kr[i];
            float e0 = fmaf(r, kv.x, xq[i].x);
            float e1 = fmaf(r, kv.y, xq[i].y);
            float e2 = fmaf(r, kv.z, xq[i].z);
            float e3 = fmaf(r, kv.w, xq[i].w);
            s0 += frcp(e0 * e0);
            s1 += frcp(e1 * e1);
            s2 += frcp(e2 * e2);
            s3 += frcp(e3 * e3);
        }
        // t1 = |aa| * rsqrt(sum 1/e^2);  prob = sigmoid(-2*artanh(min(t1,clip))) = (1-min(t1,clip))/2
        float t1 = Aiv * frsq((s0 + s1) + (s2 + s3));
        pg[n] = 0.5f * (1.f - fminf(t1, CLIP1));
    }
}

// ---------------- kernel 4: n-split midpoint GEMM, register-tiled ----------------
// grid (2 qhalf, 16 bh, NSPLIT), block 256 = (qg 0..15) x (d4 0..15).
// Thread computes 8 q x 4 d. smem: P transposed [64n][132q] + GV [64n][17 f4] + pad.
__global__ __launch_bounds__(256) void k_mid(const float* __restrict__ probs) {
    extern __shared__ float sm[];
    float* s_p = sm;                      // 64 * 132 = 8448 floats
    float4* s_gv4 = (float4*)(sm + 64 * 132);  // 64 * 17 float4
    int qh = blockIdx.x, bh = blockIdx.y, ns = blockIdx.z;
    int tid = threadIdx.x;
    int q0 = qh * 128, n0 = ns * 64;

    // stage probs [128q x 64n] -> transposed s_p[n][q]
    const float4* gp4 = (const float4*)probs;
#pragma unroll
    for (int it = 0; it < 8; it++) {
        int i = tid + it * 256;
        int q = i >> 4, n4 = i & 15;
        float4 v = gp4[(bh * SS + q0 + q) * 64 + (n0 >> 2) + n4];
        s_p[(n4 * 4 + 0) * 132 + q] = v.x;
        s_p[(n4 * 4 + 1) * 132 + q] = v.y;
        s_p[(n4 * 4 + 2) * 132 + q] = v.z;
        s_p[(n4 * 4 + 3) * 132 + q] = v.w;
    }
    // stage gv [64n x 16 f4]
    const float4* gg4 = (const float4*)(g_gv) + bh * SS * 16;
#pragma unroll
    for (int it = 0; it < 4; it++) {
        int i = tid + it * 256;
        int n = i >> 4, d4 = i & 15;
        s_gv4[n * 17 + d4] = gg4[(n0 + n) * 16 + d4];
    }
    __syncthreads();

    int qg = tid >> 4, d4 = tid & 15;
    float acc[8][4];
#pragma unroll
    for (int i = 0; i < 8; i++)
#pragma unroll
        for (int j = 0; j < 4; j++) acc[i][j] = 0.f;

#pragma unroll 4
    for (int n = 0; n < 64; n++) {
        float4 gv = s_gv4[n * 17 + d4];
        float4 pa = *(const float4*)(s_p + n * 132 + qg * 8);
        float4 pb = *(const float4*)(s_p + n * 132 + qg * 8 + 4);
        acc[0][0] = fmaf(pa.x, gv.x, acc[0][0]); acc[0][1] = fmaf(pa.x, gv.y, acc[0][1]);
        acc[0][2] = fmaf(pa.x, gv.z, acc[0][2]); acc[0][3] = fmaf(pa.x, gv.w, acc[0][3]);
        acc[1][0] = fmaf(pa.y, gv.x, acc[1][0]); acc[1][1] = fmaf(pa.y, gv.y, acc[1][1]);
        acc[1][2] = fmaf(pa.y, gv.z, acc[1][2]); acc[1][3] = fmaf(pa.y, gv.w, acc[1][3]);
        acc[2][0] = fmaf(pa.z, gv.x, acc[2][0]); acc[2][1] = fmaf(pa.z, gv.y, acc[2][1]);
        acc[2][2] = fmaf(pa.z, gv.z, acc[2][2]); acc[2][3] = fmaf(pa.z, gv.w, acc[2][3]);
        acc[3][0] = fmaf(pa.w, gv.x, acc[3][0]); acc[3][1] = fmaf(pa.w, gv.y, acc[3][1]);
        acc[3][2] = fmaf(pa.w, gv.z, acc[3][2]); acc[3][3] = fmaf(pa.w, gv.w, acc[3][3]);
        acc[4][0] = fmaf(pb.x, gv.x, acc[4][0]); acc[4][1] = fmaf(pb.x, gv.y, acc[4][1]);
        acc[4][2] = fmaf(pb.x, gv.z, acc[4][2]); acc[4][3] = fmaf(pb.x, gv.w, acc[4][3]);
        acc[5][0] = fmaf(pb.y, gv.x, acc[5][0]); acc[5][1] = fmaf(pb.y, gv.y, acc[5][1]);
        acc[5][2] = fmaf(pb.y, gv.z, acc[5][2]); acc[5][3] = fmaf(pb.y, gv.w, acc[5][3]);
        acc[6][0] = fmaf(pb.z, gv.x, acc[6][0]); acc[6][1] = fmaf(pb.z, gv.y, acc[6][1]);
        acc[6][2] = fmaf(pb.z, gv.z, acc[6][2]); acc[6][3] = fmaf(pb.z, gv.w, acc[6][3]);
        acc[7][0] = fmaf(pb.w, gv.x, acc[7][0]); acc[7][1] = fmaf(pb.w, gv.y, acc[7][1]);
        acc[7][2] = fmaf(pb.w, gv.z, acc[7][2]); acc[7][3] = fmaf(pb.w, gv.w, acc[7][3]);
    }
    float* outp = g_nomp[ns];
#pragma unroll
    for (int i = 0; i < 8; i++) {
        int row = bh * SS + q0 + qg * 8 + i;
        *(float4*)(outp + row * 64 + d4 * 4) =
            make_float4(acc[i][0], acc[i][1], acc[i][2], acc[i][3]);
    }
}

// ---------------- kernel 5: den + midpoint epilogue + expmap0 + transpose ----------------
// grid 512 (t = b*256+q), block 512.
__global__ __launch_bounds__(512) void k_final(float* __restrict__ out,
                                               const float* __restrict__ probs) {
    __shared__ float shd[16], shn[16], shu[16];
    int t = blockIdx.x;
    int b = t >> 8, q = t & 255;
    int c = threadIdx.x;
    int h = c >> 6, d = c & 63;
    int bh = b * NHEAD + h;
    int row = bh * SS + q;
    int lane = c & 31, wid = c >> 5;

    // den = sum_n probs[row,n] * gm1[bh,n]  (64 threads per h, 4 n each)
    float4 pv = ((const float4*)probs)[row * 64 + d];
    float4 g1 = ((const float4*)g_gm1)[bh * 64 + d];
    float ad = pv.x * g1.x + pv.y * g1.y + pv.z * g1.z + pv.w * g1.w;
#pragma unroll
    for (int o = 16; o > 0; o >>= 1) ad += __shfl_xor_sync(0xffffffffu, ad, o);
    if (lane == 0) shd[wid] = ad;
    __syncthreads();
    float dn0 = shd[h * 2] + shd[h * 2 + 1];
    float dn = fmaxf(fabsf(dn0), 1e-10f);
    if (dn0 < 0.f) dn = -dn;

    int nidx = row * 64 + d;
    float m = g_nomp[0][nidx] + g_nomp[1][nidx] + g_nomp[2][nidx] + g_nomp[3][nidx];
    m = m / dn;

    // per-head (64-dim) norm: mobius_scalar_mul(0.5) + logmap0
    float nn = m * m;
#pragma unroll
    for (int o = 16; o > 0; o >>= 1) nn += __shfl_xor_sync(0xffffffffu, nn, o);
    if (lane == 0) shn[wid] = nn;
    __syncthreads();
    float nm = fmaxf(sqrtf(shn[h * 2] + shn[h * 2 + 1]), EPSF);
    float f = 0.5f * atanhf(fminf(nm, CLIP1)) / nm;
    float u = f * m;

    // full-512 expmap0
    float uu = u * u;
#pragma unroll
    for (int o = 16; o > 0; o >>= 1) uu += __shfl_xor_sync(0xffffffffu, uu, o);
    if (lane == 0) shu[wid] = uu;
    __syncthreads();
    float tot = 0.f;
#pragma unroll
    for (int i = 0; i < 16; i++) tot += shu[i];
    float n = fmaxf(sqrtf(tot), EPSF);
    float f2 = tanhf(n) / n;
    out[(q * BATCH + b) * HIDN + c] = f2 * u;
}

// ---------------- launch ----------------
extern "C" void kernel_launch(void* const* d_in, const int* in_sizes, int n_in,
                              void* d_out, int out_size) {
    const float* query = (const float*)d_in[0];
    const float* Wq = (const float*)d_in[1];
    const float* bq = (const float*)d_in[2];
    const float* Wk = (const float*)d_in[3];
    const float* bk = (const float*)d_in[4];
    const float* Wv = (const float*)d_in[5];
    const float* bv = (const float*)d_in[6];
    float* out = (float*)d_out;

    const int CTXN = SS * BATCH * HIDN;      // 262144
    const int PRN = BATCH * NHEAD * SS * SS; // 1048576
    float* dctx = 0;
    float* dpro = 0;
    if (out_size >= CTXN + PRN) { dctx = out; dpro = out + CTXN; }
    else if (out_size == PRN)   { dpro = out; }
    else                        { dctx = out; }

    const int SMEM_SCORES = (256 * 68 + 256) * 4;           // 70656
    const int SMEM_MID    = (64 * 132 + 64 * 68) * 4;       // 51200
    cudaFuncSetAttribute(k_scores, cudaFuncAttributeMaxDynamicSharedMemorySize, SMEM_SCORES);
    cudaFuncSetAttribute(k_mid,    cudaFuncAttributeMaxDynamicSharedMemorySize, SMEM_MID);

    k_gemm<<<dim3(24, 8, KSPLIT), 256>>>(query, Wq, Wk, Wv);
    k_token<<<dim3(512, 3), 512>>>(query, bq, bk, bv);

    float* probs_ptr = dpro;
    if (!probs_ptr) cudaGetSymbolAddress((void**)&probs_ptr, g_probs);

    k_scores<<<dim3(8, 8, 2), 256, SMEM_SCORES>>>(probs_ptr);
    if (dctx) {
        k_mid<<<dim3(2, 16, NSPLIT), 256, SMEM_MID>>>(probs_ptr);
        k_final<<<512, 512>>>(dctx, probs_ptr);
    }
}

// round 7
// speedup vs baseline: 1.4350x; 1.1439x over previous
#include <cuda_runtime.h>
#include <cuda_bf16.h>
#include <cstdint>

#define SS 256
#define BATCH 2
#define HIDN 512
#define NHEAD 8
#define HDIM 64
#define NTOK 512
#define EPSF 1e-15f
#define CLIP1 0.9999999f
#define MAXNORM 0.996f
#define NSPLIT 4

// ---------------- device scratch ----------------
__device__ __align__(256) float g_mx[3 * NTOK * HIDN];
__device__ __align__(256) __nv_bfloat16 g_xhi[NTOK * HIDN];
__device__ __align__(256) __nv_bfloat16 g_xlo[NTOK * HIDN];
__device__ __align__(256) __nv_bfloat16 g_whi[3 * HIDN * HIDN];
__device__ __align__(256) __nv_bfloat16 g_wlo[3 * HIDN * HIDN];
__device__ __align__(256) float g_q[BATCH * NHEAD * SS * HDIM];
__device__ __align__(256) float g_k[BATCH * NHEAD * SS * HDIM];
__device__ __align__(256) float g_gv[BATCH * NHEAD * SS * HDIM];
__device__ __align__(256) float g_x2[BATCH * NHEAD * SS];
__device__ __align__(256) float g_y2[BATCH * NHEAD * SS];
__device__ __align__(256) float g_gm1[BATCH * NHEAD * SS];
__device__ __align__(256) float g_probs[BATCH * NHEAD * SS * SS];  // fallback
__device__ __align__(256) float g_nomp[NSPLIT][BATCH * NHEAD * SS * HDIM];

static __device__ __forceinline__ float frcp(float x) {
    float r; asm("rcp.approx.f32 %0, %1;" : "=f"(r) : "f"(x)); return r;
}
static __device__ __forceinline__ float frsq(float x) {
    float r; asm("rsqrt.approx.f32 %0, %1;" : "=f"(r) : "f"(x)); return r;
}
static __device__ __forceinline__ uint32_t smem_to_u32(const void* p) {
    uint32_t a;
    asm("{ .reg .u64 t; cvta.to.shared.u64 t, %1; cvt.u32.u64 %0, t; }" : "=r"(a) : "l"(p));
    return a;
}

#define LDSM4(r, a) \
    asm volatile("ldmatrix.sync.aligned.m8n8.x4.shared.b16 {%0,%1,%2,%3}, [%4];" \
                 : "=r"((r)[0]), "=r"((r)[1]), "=r"((r)[2]), "=r"((r)[3]) : "r"(a))

#define MMA16816(dd, a, b0, b1) \
    asm volatile("mma.sync.aligned.m16n8k16.row.col.f32.bf16.bf16.f32 " \
                 "{%0,%1,%2,%3}, {%4,%5,%6,%7}, {%8,%9}, {%0,%1,%2,%3};" \
                 : "+f"((dd)[0]), "+f"((dd)[1]), "+f"((dd)[2]), "+f"((dd)[3]) \
                 : "r"((a)[0]), "r"((a)[1]), "r"((a)[2]), "r"((a)[3]), \
                   "r"(b0), "r"(b1))

template <int K>
static __device__ __forceinline__ void bredK(float* vals, float* sh) {
    int lane = threadIdx.x & 31, wid = threadIdx.x >> 5;
#pragma unroll
    for (int j = 0; j < K; j++) {
        float v = vals[j];
#pragma unroll
        for (int o = 16; o > 0; o >>= 1) v += __shfl_xor_sync(0xffffffffu, v, o);
        if (lane == 0) sh[j * 16 + wid] = v;
    }
    __syncthreads();
#pragma unroll
    for (int j = 0; j < K; j++) {
        float t = 0.f;
#pragma unroll
        for (int i = 0; i < 16; i++) t += sh[j * 16 + i];
        vals[j] = t;
    }
}

// ---------------- kernel 0: fp32 -> bf16 hi/lo split ----------------
__global__ __launch_bounds__(512) void k_convert(const float* __restrict__ X,
                                                 const float* __restrict__ Wq,
                                                 const float* __restrict__ Wk,
                                                 const float* __restrict__ Wv) {
    int stride = gridDim.x * blockDim.x;
    for (int i = blockIdx.x * blockDim.x + threadIdx.x; i < 4 * 262144; i += stride) {
        int sel = i >> 18, off = i & 262143;
        const float* src = (sel == 0) ? X : ((sel == 1) ? Wq : ((sel == 2) ? Wk : Wv));
        float v = src[off];
        __nv_bfloat16 hi = __float2bfloat16(v);
        __nv_bfloat16 lo = __float2bfloat16(v - __bfloat162float(hi));
        if (sel == 0) { g_xhi[off] = hi; g_xlo[off] = lo; }
        else {
            int wo = (sel - 1) * 262144 + off;
            g_whi[wo] = hi; g_wlo[wo] = lo;
        }
    }
}

// ---------------- kernel 1: bf16-split HMMA GEMM (mma.sync, baseline ISA) ----------
// grid (8 ntile, 8 mtile, 3 p), block 256 (8 warps).
// Block tile 64m x 64n; warp tile 16m x 32n (wm = w&3, wn = w>>2).
// K = 512 in 8 chunks of 64, double-buffered smem.
// Buffer layout (32KB): Ahi@0, Alo@8192, Bhi@16384, Blo@24576.
// Rows are 64 bf16 = 128B; 16B unit u at row r stored at phys unit u^(r&7).
__global__ __launch_bounds__(256) void k_gemm_mma() {
    extern __shared__ __align__(1024) char smem[];
    int tid = threadIdx.x;
    int w = tid >> 5, lane = tid & 31;
    int n0 = blockIdx.x * 64, m0 = blockIdx.y * 64, p = blockIdx.z;
    int wm = w & 3, wn = w >> 2;
    uint32_t sb32 = smem_to_u32(smem);

    const uint4* xhi4 = (const uint4*)g_xhi;
    const uint4* xlo4 = (const uint4*)g_xlo;
    const uint4* whi4 = (const uint4*)g_whi;
    const uint4* wlo4 = (const uint4*)g_wlo;

    float d[4][4];
#pragma unroll
    for (int c = 0; c < 4; c++)
#pragma unroll
        for (int j = 0; j < 4; j++) d[c][j] = 0.f;

    auto stage = [&](int ch, int bc) {
        char* sb = smem + bc * 32768;
#pragma unroll
        for (int it = 0; it < 8; it++) {
            int i = tid + it * 256;
            int a = (i >> 9) & 1;
            int idx = i & 511;
            int r = idx >> 3, u = idx & 7;
            uint4 v; uint32_t dst;
            if (i < 1024) {
                v = (a ? xlo4 : xhi4)[(m0 + r) * 64 + ch * 8 + u];
                dst = a * 8192 + r * 128 + ((u ^ (r & 7)) << 4);
            } else {
                v = (a ? wlo4 : whi4)[p * 32768 + (n0 + r) * 64 + ch * 8 + u];
                dst = 16384 + a * 8192 + r * 128 + ((u ^ (r & 7)) << 4);
            }
            *(uint4*)(sb + dst) = v;
        }
    };

    stage(0, 0);
    __syncthreads();

#pragma unroll 1
    for (int ch = 0; ch < 8; ch++) {
        int bc = ch & 1;
        if (ch + 1 < 8) stage(ch + 1, 1 - bc);

        uint32_t abase = sb32 + bc * 32768;
        uint32_t bbase = abase + 16384;

        // A lane address components (constant across kk except unit)
        int ar = wm * 16 + (lane & 15);
        int asel = lane >> 4;               // 0/1 -> k half
        // B lane address components
        int bsel = lane >> 4;               // 0/1 -> which n8 col of the pair
        int nkh = (lane >> 3) & 1;          // k half
        int nrl = lane & 7;

#pragma unroll
        for (int kk = 0; kk < 4; kk++) {
            int ub = kk * 2;
            uint32_t ah[4], al[4];
            {
                int au = ub + asel;
                uint32_t aaddr = abase + ar * 128 + ((au ^ (ar & 7)) << 4);
                LDSM4(ah, aaddr);
                LDSM4(al, aaddr + 8192);
            }
#pragma unroll
            for (int cp = 0; cp < 2; cp++) {
                int cc = cp * 2 + bsel;
                int nr = wn * 32 + cc * 8 + nrl;
                int bu = ub + nkh;
                uint32_t baddr = bbase + nr * 128 + ((bu ^ (nr & 7)) << 4);
                uint32_t bh[4], bl[4];
                LDSM4(bh, baddr);
                LDSM4(bl, baddr + 8192);
                // D += Ahi*Bhi + Ahi*Blo + Alo*Bhi
                MMA16816(d[2 * cp],     ah, bh[0], bh[1]);
                MMA16816(d[2 * cp + 1], ah, bh[2], bh[3]);
                MMA16816(d[2 * cp],     ah, bl[0], bl[1]);
                MMA16816(d[2 * cp + 1], ah, bl[2], bl[3]);
                MMA16816(d[2 * cp],     al, bh[0], bh[1]);
                MMA16816(d[2 * cp + 1], al, bh[2], bh[3]);
            }
        }
        __syncthreads();
    }

    // write out: thread t holds rows g, g+8 (g = lane>>2), cols (lane&3)*2, +1 per n8 col
    float* out = g_mx + p * (NTOK * HIDN);
    int g = lane >> 2, c2 = (lane & 3) * 2;
    int row = m0 + wm * 16 + g;
#pragma unroll
    for (int c = 0; c < 4; c++) {
        int col = n0 + wn * 32 + c * 8 + c2;
        *(float2*)(out + row * 512 + col) = make_float2(d[c][0], d[c][1]);
        *(float2*)(out + (row + 8) * 512 + col) = make_float2(d[c][2], d[c][3]);
    }
}

// ---------------- kernel 2: per-token manifold nonlinearity ----------------
__global__ __launch_bounds__(512) void k_token(const float* __restrict__ query,
                                               const float* __restrict__ bq,
                                               const float* __restrict__ bk,
                                               const float* __restrict__ bv) {
    __shared__ float sh[48];
    int tt = blockIdx.x, p = blockIdx.y, c = threadIdx.x;
    const float* bias = (p == 0) ? bq : ((p == 1) ? bk : bv);

    float x  = query[tt * 512 + c];
    float mx = g_mx[p * (NTOK * HIDN) + tt * 512 + c];
    float bb = bias[c];

    float r3[3] = {x * x, mx * mx, bb * bb};
    bredK<3>(r3, sh);
    __syncthreads();

    float xn = fmaxf(sqrtf(r3[0]), EPSF);
    float mn = fmaxf(sqrtf(r3[1]), EPSF);
    float b2 = r3[2];
    float sc = tanhf(mn / xn * atanhf(fminf(xn, CLIP1))) / mn;
    float res = sc * mx;

    float r2[2] = {res * bb, res * res};
    bredK<2>(r2, sh);
    __syncthreads();
    float rb = r2[0], rr = r2[1];

    float A  = 1.f + 2.f * rb + b2;
    float Bc = 1.f - rr;
    float den = fmaxf(1.f + 2.f * rb + rr * b2, EPSF);
    float y = (A * res + Bc * bb) / den;

    float r1[1] = {y * y};
    bredK<1>(r1, sh);
    __syncthreads();
    float n = fmaxf(sqrtf(r1[0]), EPSF);
    if (n > MAXNORM) { y *= MAXNORM / n; n = MAXNORM; }

    float lf = atanhf(fminf(n, CLIP1)) / n;
    float u = lf * y;

    float uu = u * u;
#pragma unroll
    for (int o = 16; o > 0; o >>= 1) uu += __shfl_xor_sync(0xffffffffu, uu, o);
    int lane = c & 31, wid = c >> 5;
    if (lane == 0) sh[wid] = uu;
    __syncthreads();
    int chunk = c >> 6;
    float cs = sh[chunk * 2] + sh[chunk * 2 + 1];
    float n64 = fmaxf(sqrtf(cs), EPSF);
    float t = tanhf(n64);
    float e = t / n64 * u;

    int s = tt >> 1, b = tt & 1;
    int h = s >> 5, s2 = ((s & 31) << 3) | chunk, d = c & 63;
    int hidx = (b * NHEAD + h) * SS + s2;
    int idx = hidx * 64 + d;
    if (p == 0) {
        g_q[idx] = e;
        if (d == 0) g_x2[hidx] = t * t;
    } else if (p == 1) {
        g_k[idx] = e;
        if (d == 0) g_y2[hidx] = t * t;
    } else {
        float gamma = 2.f / fmaxf(1.f - t * t, EPSF);
        g_gv[idx] = gamma * e;
        if (d == 0) g_gm1[hidx] = gamma - 1.f;
    }
}

// ---------------- kernel 3: pairwise scores -> probs ----------------
__global__ __launch_bounds__(256) void k_scores(float* __restrict__ probs) {
    extern __shared__ float sm[];
    float* s_kl = sm;
    float* s_y2 = sm + 256 * 68;
    int b = blockIdx.z, h = blockIdx.y, qt = blockIdx.x;
    int bh = b * NHEAD + h;
    int tid = threadIdx.x;

    const float4* gk4 = (const float4*)(g_k) + bh * SS * 16;
    float4* skl4 = (float4*)s_kl;
    for (int i = tid; i < SS * 16; i += 256) {
        int n = i >> 4, d4 = i & 15;
        skl4[n * 17 + d4] = gk4[i];
    }
    for (int i = tid; i < SS; i += 256) s_y2[i] = g_y2[bh * SS + i];
    __syncthreads();

    int q = qt * 32 + (tid >> 3);
    int nset = tid & 7;

    float4 xq[16];
    const float4* gq4 = (const float4*)(g_q) + (bh * SS + q) * 16;
#pragma unroll
    for (int i = 0; i < 16; i++) xq[i] = gq4[i];
    float x2 = g_x2[bh * SS + q];
    float Bc = 1.f - x2;

    float* pg = probs + (bh * SS + q) * SS;

#pragma unroll 1
    for (int j = 0; j < 32; j++) {
        int n = nset + (j << 3);
        const float4* kr = skl4 + n * 17;

        float a0 = 0.f, a1 = 0.f, a2 = 0.f, a3 = 0.f;
#pragma unroll
        for (int i = 0; i < 16; i++) {
            float4 kv = kr[i];
            a0 = fmaf(xq[i].x, kv.x, a0);
            a1 = fmaf(xq[i].y, kv.y, a1);
            a2 = fmaf(xq[i].z, kv.z, a2);
            a3 = fmaf(xq[i].w, kv.w, a3);
        }
        float xy = -((a0 + a1) + (a2 + a3));
        float y2 = s_y2[n];
        float base = fmaf(2.f, xy, 1.f);
        float A = base + y2;
        float den = fmaxf(fmaf(x2, y2, base), EPSF);
        float Aiv = A * frcp(den);
        float r = -Bc * frcp(A);

        float s0 = 0.f, s1 = 0.f, s2 = 0.f, s3 = 0.f;
#pragma unroll
        for (int i = 0; i < 16; i++) {
            float4 kv = kr[i];
            float e0 = fmaf(r, kv.x, xq[i].x);
            float e1 = fmaf(r, kv.y, xq[i].y);
            float e2 = fmaf(r, kv.z, xq[i].z);
            float e3 = fmaf(r, kv.w, xq[i].w);
            s0 += frcp(e0 * e0);
            s1 += frcp(e1 * e1);
            s2 += frcp(e2 * e2);
            s3 += frcp(e3 * e3);
        }
        float t1 = Aiv * frsq((s0 + s1) + (s2 + s3));
        pg[n] = 0.5f * (1.f - fminf(t1, CLIP1));
    }
}

// ---------------- kernel 4: n-split midpoint GEMM, register-tiled ----------------
__global__ __launch_bounds__(256) void k_mid(const float* __restrict__ probs) {
    extern __shared__ float sm[];
    float* s_p = sm;
    float4* s_gv4 = (float4*)(sm + 64 * 132);
    int qh = blockIdx.x, bh = blockIdx.y, ns = blockIdx.z;
    int tid = threadIdx.x;
    int q0 = qh * 128, n0 = ns * 64;

    const float4* gp4 = (const float4*)probs;
#pragma unroll
    for (int it = 0; it < 8; it++) {
        int i = tid + it * 256;
        int q = i >> 4, n4 = i & 15;
        float4 v = gp4[(bh * SS + q0 + q) * 64 + (n0 >> 2) + n4];
        s_p[(n4 * 4 + 0) * 132 + q] = v.x;
        s_p[(n4 * 4 + 1) * 132 + q] = v.y;
        s_p[(n4 * 4 + 2) * 132 + q] = v.z;
        s_p[(n4 * 4 + 3) * 132 + q] = v.w;
    }
    const float4* gg4 = (const float4*)(g_gv) + bh * SS * 16;
#pragma unroll
    for (int it = 0; it < 4; it++) {
        int i = tid + it * 256;
        int n = i >> 4, d4 = i & 15;
        s_gv4[n * 17 + d4] = gg4[(n0 + n) * 16 + d4];
    }
    __syncthreads();

    int qg = tid >> 4, d4 = tid & 15;
    float acc[8][4];
#pragma unroll
    for (int i = 0; i < 8; i++)
#pragma unroll
        for (int j = 0; j < 4; j++) acc[i][j] = 0.f;

#pragma unroll 4
    for (int n = 0; n < 64; n++) {
        float4 gv = s_gv4[n * 17 + d4];
        float4 pa = *(const float4*)(s_p + n * 132 + qg * 8);
        float4 pb = *(const float4*)(s_p + n * 132 + qg * 8 + 4);
        acc[0][0] = fmaf(pa.x, gv.x, acc[0][0]); acc[0][1] = fmaf(pa.x, gv.y, acc[0][1]);
        acc[0][2] = fmaf(pa.x, gv.z, acc[0][2]); acc[0][3] = fmaf(pa.x, gv.w, acc[0][3]);
        acc[1][0] = fmaf(pa.y, gv.x, acc[1][0]); acc[1][1] = fmaf(pa.y, gv.y, acc[1][1]);
        acc[1][2] = fmaf(pa.y, gv.z, acc[1][2]); acc[1][3] = fmaf(pa.y, gv.w, acc[1][3]);
        acc[2][0] = fmaf(pa.z, gv.x, acc[2][0]); acc[2][1] = fmaf(pa.z, gv.y, acc[2][1]);
        acc[2][2] = fmaf(pa.z, gv.z, acc[2][2]); acc[2][3] = fmaf(pa.z, gv.w, acc[2][3]);
        acc[3][0] = fmaf(pa.w, gv.x, acc[3][0]); acc[3][1] = fmaf(pa.w, gv.y, acc[3][1]);
        acc[3][2] = fmaf(pa.w, gv.z, acc[3][2]); acc[3][3] = fmaf(pa.w, gv.w, acc[3][3]);
        acc[4][0] = fmaf(pb.x, gv.x, acc[4][0]); acc[4][1] = fmaf(pb.x, gv.y, acc[4][1]);
        acc[4][2] = fmaf(pb.x, gv.z, acc[4][2]); acc[4][3] = fmaf(pb.x, gv.w, acc[4][3]);
        acc[5][0] = fmaf(pb.y, gv.x, acc[5][0]); acc[5][1] = fmaf(pb.y, gv.y, acc[5][1]);
        acc[5][2] = fmaf(pb.y, gv.z, acc[5][2]); acc[5][3] = fmaf(pb.y, gv.w, acc[5][3]);
        acc[6][0] = fmaf(pb.z, gv.x, acc[6][0]); acc[6][1] = fmaf(pb.z, gv.y, acc[6][1]);
        acc[6][2] = fmaf(pb.z, gv.z, acc[6][2]); acc[6][3] = fmaf(pb.z, gv.w, acc[6][3]);
        acc[7][0] = fmaf(pb.w, gv.x, acc[7][0]); acc[7][1] = fmaf(pb.w, gv.y, acc[7][1]);
        acc[7][2] = fmaf(pb.w, gv.z, acc[7][2]); acc[7][3] = fmaf(pb.w, gv.w, acc[7][3]);
    }
    float* outp = g_nomp[ns];
#pragma unroll
    for (int i = 0; i < 8; i++) {
        int row = bh * SS + q0 + qg * 8 + i;
        *(float4*)(outp + row * 64 + d4 * 4) =
            make_float4(acc[i][0], acc[i][1], acc[i][2], acc[i][3]);
    }
}

// ---------------- kernel 5: den + epilogue + expmap0 + transpose ----------------
__global__ __launch_bounds__(512) void k_final(float* __restrict__ out,
                                               const float* __restrict__ probs) {
    __shared__ float shd[16], shn[16], shu[16];
    int t = blockIdx.x;
    int b = t >> 8, q = t & 255;
    int c = threadIdx.x;
    int h = c >> 6, d = c & 63;
    int bh = b * NHEAD + h;
    int row = bh * SS + q;
    int lane = c & 31, wid = c >> 5;

    float4 pv = ((const float4*)probs)[row * 64 + d];
    float4 g1 = ((const float4*)g_gm1)[bh * 64 + d];
    float ad = pv.x * g1.x + pv.y * g1.y + pv.z * g1.z + pv.w * g1.w;
#pragma unroll
    for (int o = 16; o > 0; o >>= 1) ad += __shfl_xor_sync(0xffffffffu, ad, o);
    if (lane == 0) shd[wid] = ad;
    __syncthreads();
    float dn0 = shd[h * 2] + shd[h * 2 + 1];
    float dn = fmaxf(fabsf(dn0), 1e-10f);
    if (dn0 < 0.f) dn = -dn;

    int nidx = row * 64 + d;
    float m = g_nomp[0][nidx] + g_nomp[1][nidx] + g_nomp[2][nidx] + g_nomp[3][nidx];
    m = m / dn;

    float nn = m * m;
#pragma unroll
    for (int o = 16; o > 0; o >>= 1) nn += __shfl_xor_sync(0xffffffffu, nn, o);
    if (lane == 0) shn[wid] = nn;
    __syncthreads();
    float nm = fmaxf(sqrtf(shn[h * 2] + shn[h * 2 + 1]), EPSF);
    float f = 0.5f * atanhf(fminf(nm, CLIP1)) / nm;
    float u = f * m;

    float uu = u * u;
#pragma unroll
    for (int o = 16; o > 0; o >>= 1) uu += __shfl_xor_sync(0xffffffffu, uu, o);
    if (lane == 0) shu[wid] = uu;
    __syncthreads();
    float tot = 0.f;
#pragma unroll
    for (int i = 0; i < 16; i++) tot += shu[i];
    float n = fmaxf(sqrtf(tot), EPSF);
    float f2 = tanhf(n) / n;
    out[(q * BATCH + b) * HIDN + c] = f2 * u;
}

// ---------------- launch ----------------
extern "C" void kernel_launch(void* const* d_in, const int* in_sizes, int n_in,
                              void* d_out, int out_size) {
    const float* query = (const float*)d_in[0];
    const float* Wq = (const float*)d_in[1];
    const float* bq = (const float*)d_in[2];
    const float* Wk = (const float*)d_in[3];
    const float* bk = (const float*)d_in[4];
    const float* Wv = (const float*)d_in[5];
    const float* bv = (const float*)d_in[6];
    float* out = (float*)d_out;

    const int CTXN = SS * BATCH * HIDN;      // 262144
    const int PRN = BATCH * NHEAD * SS * SS; // 1048576
    float* dctx = 0;
    float* dpro = 0;
    if (out_size >= CTXN + PRN) { dctx = out; dpro = out + CTXN; }
    else if (out_size == PRN)   { dpro = out; }
    else                        { dctx = out; }

    const int SMEM_MMA    = 65536;
    const int SMEM_SCORES = (256 * 68 + 256) * 4;           // 70656
    const int SMEM_MID    = (64 * 132 + 64 * 68) * 4;       // 51200
    cudaFuncSetAttribute(k_gemm_mma, cudaFuncAttributeMaxDynamicSharedMemorySize, SMEM_MMA);
    cudaFuncSetAttribute(k_scores,   cudaFuncAttributeMaxDynamicSharedMemorySize, SMEM_SCORES);
    cudaFuncSetAttribute(k_mid,      cudaFuncAttributeMaxDynamicSharedMemorySize, SMEM_MID);

    k_convert<<<512, 512>>>(query, Wq, Wk, Wv);
    k_gemm_mma<<<dim3(8, 8, 3), 256, SMEM_MMA>>>();
    k_token<<<dim3(512, 3), 512>>>(query, bq, bk, bv);

    float* probs_ptr = dpro;
    if (!probs_ptr) cudaGetSymbolAddress((void**)&probs_ptr, g_probs);

    k_scores<<<dim3(8, 8, 2), 256, SMEM_SCORES>>>(probs_ptr);
    if (dctx) {
        k_mid<<<dim3(2, 16, NSPLIT), 256, SMEM_MID>>>(probs_ptr);
        k_final<<<512, 512>>>(dctx, probs_ptr);
    }
}